// round 1
// baseline (speedup 1.0000x reference)
#include <cuda_runtime.h>
#include <cstdint>

#define NN 50000
#define NE 800000
#define D  128

static __device__ __forceinline__ float rrelu_f(float x) {
    const float SLOPE = (1.0f/8.0f + 1.0f/3.0f) * 0.5f;
    return x >= 0.0f ? x : x * SLOPE;
}

// ---------------- scratch layout (floats) ----------------
#define ND        (NN * D)                 // 6,400,000
#define OFF_EAGG  0
#define OFF_SAGG0 (ND)
#define OFF_SAGG1 (2 * ND)
#define OFF_CNT   (3 * ND)                 // 50048 slots
#define ZERO_N    (3 * ND + 50048)         // region to zero each call
#define OFF_EW0   (ZERO_N)
#define OFF_EW1   (OFF_EW0 + ND)
#define OFF_T0A   (OFF_EW1 + ND)
#define OFF_T0B   (OFF_T0A + ND)
#define OFF_T1A   (OFF_T0B + ND)
#define OFF_T1B   (OFF_T1A + ND)
#define OFF_HCAT  (OFF_T1B + ND)           // 50k x 256
#define SCRATCH_N (OFF_HCAT + 2 * ND)

__device__ float g_scratch[SCRATCH_N];

// ---------------- vector RED helper ----------------
__device__ __forceinline__ void red_add_v4(float* p, float4 v) {
    asm volatile("red.global.add.v4.f32 [%0], {%1,%2,%3,%4};"
                 :: "l"(p), "f"(v.x), "f"(v.y), "f"(v.z), "f"(v.w)
                 : "memory");
}

// ---------------- zero ----------------
__global__ void zero_kernel(float4* p, int n4) {
    int i = blockIdx.x * blockDim.x + threadIdx.x;
    if (i < n4) p[i] = make_float4(0.f, 0.f, 0.f, 0.f);
}

// ---------------- edge-feature scatter + degree ----------------
// one warp per edge: Eagg[dst] += e[edge]; cnt[dst] += 1
__global__ void scatter_edges(const float* __restrict__ e,
                              const int* __restrict__ dst,
                              float* __restrict__ Eagg,
                              float* __restrict__ cnt) {
    int w    = (blockIdx.x * blockDim.x + threadIdx.x) >> 5;
    int lane = threadIdx.x & 31;
    if (w >= NE) return;
    int d = __ldg(dst + w);
    float4 v = *reinterpret_cast<const float4*>(e + (size_t)w * D + lane * 4);
    red_add_v4(Eagg + (size_t)d * D + lane * 4, v);
    if (lane == 0)
        atomicAdd(cnt + d, 1.0f);
}

// ---------------- projected-node scatter ----------------
// one warp per edge: Sagg[dst] += T[src]
__global__ void scatter_T(const float* __restrict__ T,
                          const int* __restrict__ src,
                          const int* __restrict__ dst,
                          float* __restrict__ Sagg) {
    int w    = (blockIdx.x * blockDim.x + threadIdx.x) >> 5;
    int lane = threadIdx.x & 31;
    if (w >= NE) return;
    int s = __ldg(src + w);
    int d = __ldg(dst + w);
    float4 v = *reinterpret_cast<const float4*>(T + (size_t)s * D + lane * 4);
    red_add_v4(Sagg + (size_t)d * D + lane * 4, v);
}

// ---------------- SIMT fp32 GEMM: C = A(lda) @ B[K,N] (+bias) ----------------
#define BM 128
#define BN 128
#define BK 8
#define TM 8
#define TN 8

__global__ __launch_bounds__(256, 2)
void sgemm(const float* __restrict__ A, int lda,
           const float* __restrict__ B,
           const float* __restrict__ bias,   // may be nullptr
           float* __restrict__ C,            // ldc = N
           int M, int N, int K) {
    __shared__ float As[BK][BM];
    __shared__ float Bs[BK][BN];

    int bm = blockIdx.y * BM;
    int bn = blockIdx.x * BN;
    int tid = threadIdx.x;

    int arow = tid >> 1;
    int acol = (tid & 1) * 4;
    int brow = tid >> 5;
    int bcol = (tid & 31) * 4;

    int ty = tid >> 4;   // 0..15
    int tx = tid & 15;   // 0..15

    float acc[TM][TN];
#pragma unroll
    for (int i = 0; i < TM; i++)
#pragma unroll
        for (int j = 0; j < TN; j++) acc[i][j] = 0.f;

    for (int k0 = 0; k0 < K; k0 += BK) {
        float4 av = make_float4(0.f, 0.f, 0.f, 0.f);
        int gr = bm + arow;
        if (gr < M)
            av = *reinterpret_cast<const float4*>(A + (size_t)gr * lda + k0 + acol);
        As[acol + 0][arow] = av.x;
        As[acol + 1][arow] = av.y;
        As[acol + 2][arow] = av.z;
        As[acol + 3][arow] = av.w;

        float4 bv = *reinterpret_cast<const float4*>(B + (size_t)(k0 + brow) * N + bn + bcol);
        *reinterpret_cast<float4*>(&Bs[brow][bcol]) = bv;
        __syncthreads();

#pragma unroll
        for (int kk = 0; kk < BK; kk++) {
            float4 a0 = *reinterpret_cast<const float4*>(&As[kk][ty * TM]);
            float4 a1 = *reinterpret_cast<const float4*>(&As[kk][ty * TM + 4]);
            float4 b0 = *reinterpret_cast<const float4*>(&Bs[kk][tx * TN]);
            float4 b1 = *reinterpret_cast<const float4*>(&Bs[kk][tx * TN + 4]);
            float ar[TM] = {a0.x, a0.y, a0.z, a0.w, a1.x, a1.y, a1.z, a1.w};
            float br[TN] = {b0.x, b0.y, b0.z, b0.w, b1.x, b1.y, b1.z, b1.w};
#pragma unroll
            for (int i = 0; i < TM; i++)
#pragma unroll
                for (int j = 0; j < TN; j++)
                    acc[i][j] += ar[i] * br[j];
        }
        __syncthreads();
    }

#pragma unroll
    for (int i = 0; i < TM; i++) {
        int r = bm + ty * TM + i;
        if (r >= M) continue;
        float* crow = C + (size_t)r * N + bn + tx * TN;
#pragma unroll
        for (int j = 0; j < TN; j++) {
            float v = acc[i][j];
            if (bias) v += __ldg(bias + bn + tx * TN + j);
            crow[j] = v;
        }
    }
}

// ---------------- layer epilogue ----------------
// h = rrelu( (Sagg+EW)/max(cnt,1) + (cnt>0)*bn + Tb + bl ), written to hcat (ld=256)
__global__ void layer_epi(const float* __restrict__ Sagg,
                          const float* __restrict__ EW,
                          const float* __restrict__ Tb,
                          const float* __restrict__ cnt,
                          const float* __restrict__ bn,
                          const float* __restrict__ bl,
                          float* __restrict__ hcat, int col_off) {
    int idx = blockIdx.x * blockDim.x + threadIdx.x;
    if (idx >= ND) return;
    int node = idx >> 7;
    int c    = idx & (D - 1);
    float cn  = cnt[node];
    float inv = 1.0f / fmaxf(cn, 1.0f);
    float pre = (Sagg[idx] + EW[idx]) * inv
              + (cn > 0.f ? __ldg(bn + c) : 0.f)
              + Tb[idx] + __ldg(bl + c);
    hcat[(size_t)node * (2 * D) + col_off + c] = rrelu_f(pre);
}

// ---------------- launch ----------------
extern "C" void kernel_launch(void* const* d_in, const int* in_sizes, int n_in,
                              void* d_out, int out_size) {
    const float* x   = (const float*)d_in[0];
    const float* e   = (const float*)d_in[1];
    const int*   src = (const int*)d_in[2];
    const int*   dst = (const int*)d_in[3];
    const float* Wn0 = (const float*)d_in[4];
    const float* bn0 = (const float*)d_in[5];
    const float* Wl0 = (const float*)d_in[6];
    const float* bl0 = (const float*)d_in[7];
    const float* Wn1 = (const float*)d_in[8];
    const float* bn1 = (const float*)d_in[9];
    const float* Wl1 = (const float*)d_in[10];
    const float* bl1 = (const float*)d_in[11];
    const float* Wo  = (const float*)d_in[12];
    const float* bo  = (const float*)d_in[13];
    float* out = (float*)d_out;

    float* S = nullptr;
    cudaGetSymbolAddress((void**)&S, g_scratch);

    float* Eagg  = S + OFF_EAGG;
    float* Sagg0 = S + OFF_SAGG0;
    float* Sagg1 = S + OFF_SAGG1;
    float* cnt   = S + OFF_CNT;
    float* EW0   = S + OFF_EW0;
    float* EW1   = S + OFF_EW1;
    float* T0A   = S + OFF_T0A;
    float* T0B   = S + OFF_T0B;
    float* T1A   = S + OFF_T1A;
    float* T1B   = S + OFF_T1B;
    float* HCAT  = S + OFF_HCAT;

    // 1. zero accumulators
    {
        int n4 = ZERO_N / 4;
        zero_kernel<<<(n4 + 255) / 256, 256>>>((float4*)S, n4);
    }

    // 2. edge scatter + degree (layer-invariant)
    {
        int threads = 256;
        int blocks  = (NE * 32 + threads - 1) / threads;
        scatter_edges<<<blocks, threads>>>(e, dst, Eagg, cnt);
    }

    dim3 g1(1, (NN + BM - 1) / BM);  // N=128
    // 3. edge-aggregate projections (both layers)
    sgemm<<<g1, 256>>>(Eagg, D, Wn0 + D * D, nullptr, EW0, NN, D, D);
    sgemm<<<g1, 256>>>(Eagg, D, Wn1 + D * D, nullptr, EW1, NN, D, D);

    // 4. layer 0 node projections
    sgemm<<<g1, 256>>>(x, D, Wn0, nullptr, T0A, NN, D, D);  // h @ Wn0[:D]
    sgemm<<<g1, 256>>>(x, D, Wl0, nullptr, T0B, NN, D, D);  // h @ Wl0

    // 5. layer 0 scatter + epilogue
    {
        int threads = 256;
        int blocks  = (NE * 32 + threads - 1) / threads;
        scatter_T<<<blocks, threads>>>(T0A, src, dst, Sagg0);
    }
    layer_epi<<<(ND + 255) / 256, 256>>>(Sagg0, EW0, T0B, cnt, bn0, bl0, HCAT, 0);

    // 6. layer 1 node projections (h1 = HCAT cols [0,128), lda=256)
    sgemm<<<g1, 256>>>(HCAT, 2 * D, Wn1, nullptr, T1A, NN, D, D);
    sgemm<<<g1, 256>>>(HCAT, 2 * D, Wl1, nullptr, T1B, NN, D, D);

    // 7. layer 1 scatter + epilogue
    {
        int threads = 256;
        int blocks  = (NE * 32 + threads - 1) / threads;
        scatter_T<<<blocks, threads>>>(T1A, src, dst, Sagg1);
    }
    layer_epi<<<(ND + 255) / 256, 256>>>(Sagg1, EW1, T1B, cnt, bn1, bl1, HCAT, D);

    // 8. output projection: out = hcat @ Wo + bo  (K=256)
    sgemm<<<g1, 256>>>(HCAT, 2 * D, Wo, bo, out, NN, D, 2 * D);
}

// round 3
// speedup vs baseline: 1.2918x; 1.2918x over previous
#include <cuda_runtime.h>
#include <cuda_bf16.h>
#include <cstdint>

#define NN 50000
#define NE 800000
#define D  128

static __device__ __forceinline__ float rrelu_f(float x) {
    const float SLOPE = (1.0f/8.0f + 1.0f/3.0f) * 0.5f;
    return x >= 0.0f ? x : x * SLOPE;
}

// ---------------- scratch layout (floats) ----------------
#define ND        (NN * D)                 // 6,400,000
#define OFF_EAGG  0
#define OFF_SAGG0 (ND)
#define OFF_SAGG1 (2 * ND)
#define OFF_CNT   (3 * ND)                 // 50048 slots
#define ZERO_N    (3 * ND + 50048)
#define OFF_P0    (ZERO_N)                 // 50k x 256: [T0A | T0B]
#define OFF_PE    (OFF_P0 + 2 * ND)        // 50k x 256: [EW0 | EW1]
#define OFF_P1    (OFF_PE + 2 * ND)        // 50k x 256: [T1A | T1B]
#define OFF_HCAT  (OFF_P1 + 2 * ND)        // 50k x 256
#define SCRATCH_N (OFF_HCAT + 2 * ND)

__device__ float g_scratch[SCRATCH_N];

// bf16 weight images: 8 chunks x 64KB. Chunk = hi[128][128] bf16 (Bt layout
// [n][k]) then lo[128][128]. Chunk order:
// 0:Wn0u 1:Wl0 2:Wn0e 3:Wn1e 4:Wn1u 5:Wl1 6:Wo[0:128] 7:Wo[128:256]
__device__ __align__(16) unsigned char g_bimg[8 * 65536];

// ---------------- PTX helpers ----------------
__device__ __forceinline__ uint32_t smem_u32(const void* p) {
    uint32_t a;
    asm("{ .reg .u64 t; cvta.to.shared.u64 t, %1; cvt.u32.u64 %0, t; }" : "=r"(a) : "l"(p));
    return a;
}

__device__ __forceinline__ void ldsm_x4(uint32_t addr, uint32_t* r) {
    asm volatile("ldmatrix.sync.aligned.m8n8.x4.shared.b16 {%0,%1,%2,%3}, [%4];"
                 : "=r"(r[0]), "=r"(r[1]), "=r"(r[2]), "=r"(r[3]) : "r"(addr));
}

__device__ __forceinline__ void mma_bf16(float* c, const uint32_t* a,
                                         uint32_t b0, uint32_t b1) {
    asm volatile("mma.sync.aligned.m16n8k16.row.col.f32.bf16.bf16.f32 "
                 "{%0,%1,%2,%3}, {%4,%5,%6,%7}, {%8,%9}, {%0,%1,%2,%3};"
                 : "+f"(c[0]), "+f"(c[1]), "+f"(c[2]), "+f"(c[3])
                 : "r"(a[0]), "r"(a[1]), "r"(a[2]), "r"(a[3]), "r"(b0), "r"(b1));
}

__device__ __forceinline__ void red_add_v4(float* p, float4 v) {
    asm volatile("red.global.add.v4.f32 [%0], {%1,%2,%3,%4};"
                 :: "l"(p), "f"(v.x), "f"(v.y), "f"(v.z), "f"(v.w)
                 : "memory");
}

// ---------------- zero ----------------
__global__ void zero_kernel(float4* p, int n4) {
    int i = blockIdx.x * blockDim.x + threadIdx.x;
    if (i < n4) p[i] = make_float4(0.f, 0.f, 0.f, 0.f);
}

// ---------------- edge-feature scatter + degree ----------------
__global__ void scatter_edges(const float* __restrict__ e,
                              const int* __restrict__ dst,
                              float* __restrict__ Eagg,
                              float* __restrict__ cnt) {
    int w    = (blockIdx.x * blockDim.x + threadIdx.x) >> 5;
    int lane = threadIdx.x & 31;
    if (w >= NE) return;
    int d = __ldg(dst + w);
    float4 v = *reinterpret_cast<const float4*>(e + (size_t)w * D + lane * 4);
    red_add_v4(Eagg + (size_t)d * D + lane * 4, v);
    if (lane == 0)
        atomicAdd(cnt + d, 1.0f);
}

// ---------------- projected-node scatter (T has leading dim ld) ----------------
__global__ void scatter_T(const float* __restrict__ T, int ld,
                          const int* __restrict__ src,
                          const int* __restrict__ dst,
                          float* __restrict__ Sagg) {
    int w    = (blockIdx.x * blockDim.x + threadIdx.x) >> 5;
    int lane = threadIdx.x & 31;
    if (w >= NE) return;
    int s = __ldg(src + w);
    int d = __ldg(dst + w);
    float4 v = *reinterpret_cast<const float4*>(T + (size_t)s * ld + lane * 4);
    red_add_v4(Sagg + (size_t)d * D + lane * 4, v);
}

// ---------------- weight image prep ----------------
// 8 blocks x 128 threads; block ci prepares chunk ci: Bt[n][k] bf16 hi+lo.
__global__ void prep_B(const float* __restrict__ Wn0, const float* __restrict__ Wl0,
                       const float* __restrict__ Wn1, const float* __restrict__ Wl1,
                       const float* __restrict__ Wo, unsigned char* __restrict__ img) {
    int ci = blockIdx.x;
    const float* W;
    switch (ci) {
        case 0: W = Wn0; break;
        case 1: W = Wl0; break;
        case 2: W = Wn0 + 128 * 128; break;
        case 3: W = Wn1 + 128 * 128; break;
        case 4: W = Wn1; break;
        case 5: W = Wl1; break;
        case 6: W = Wo; break;
        default: W = Wo + 128 * 128; break;
    }
    unsigned char* hi_img = img + ci * 65536;
    unsigned char* lo_img = hi_img + 32768;

    __shared__ float sw[64][129];
    int t = threadIdx.x;  // 128
    for (int kt = 0; kt < 2; kt++) {
        for (int i = t; i < 64 * 128; i += 128)
            sw[i >> 7][i & 127] = W[kt * 64 * 128 + i];
        __syncthreads();
        int n = t;
#pragma unroll
        for (int u = 0; u < 8; u++) {
            union { __nv_bfloat16 h[8]; uint4 v; } hi;
            union { __nv_bfloat16 h[8]; uint4 v; } lo;
#pragma unroll
            for (int j = 0; j < 8; j++) {
                float f = sw[u * 8 + j][n];
                __nv_bfloat16 hb = __float2bfloat16(f);
                hi.h[j] = hb;
                lo.h[j] = __float2bfloat16(f - __bfloat162float(hb));
            }
            uint32_t off = (uint32_t)(n * 256 + kt * 128 + u * 16);
            *reinterpret_cast<uint4*>(hi_img + off) = hi.v;
            *reinterpret_cast<uint4*>(lo_img + off) = lo.v;
        }
        __syncthreads();
    }
}

// ---------------- HMMA bf16x3 GEMM ----------------
// C[:, bn:bn+128] = sum_kc A[:, kc*128:(kc+1)*128] @ Bchunk(bn, kc)  (+bias)
// smem: A hi/lo [128][136] bf16, B hi/lo [128][136] bf16
#define SA_HI 0
#define SA_LO 34816
#define SB_HI 69632
#define SB_LO 104448
#define SM_TOTAL 139264
#define LDE 136  // smem leading dim in elements (272 bytes)

__global__ __launch_bounds__(256, 1)
void gemm_mma(const float* __restrict__ A, int lda,
              const unsigned char* __restrict__ Bimg, int KB,
              float* __restrict__ C, int ldc,
              const float* __restrict__ bias, int M) {
    extern __shared__ unsigned char smem[];
    uint32_t sb = smem_u32(smem);
    int tid  = threadIdx.x;
    int lane = tid & 31;
    int wid  = tid >> 5;
    int wm   = wid & 3;       // 4 m-tiles of 32 rows
    int wn   = wid >> 2;      // 2 n-tiles of 64 cols
    int bm   = blockIdx.y * 128;
    int bn   = blockIdx.x * 128;

    float acc[2][8][4];
#pragma unroll
    for (int mi = 0; mi < 2; mi++)
#pragma unroll
        for (int ni = 0; ni < 8; ni++)
#pragma unroll
            for (int q = 0; q < 4; q++) acc[mi][ni][q] = 0.f;

    // per-thread load roles
    int r    = tid >> 1;       // 0..127
    int half = tid & 1;        // 0/1 (64-elem halves)
    bool valid = (bm + r) < M;

    for (int kc = 0; kc < KB; kc++) {
        __syncthreads();
        // ---- A chunk: global f32 -> smem bf16 hi/lo ----
        {
            const float4* ap = reinterpret_cast<const float4*>(
                A + (size_t)(bm + r) * lda + kc * 128 + half * 64);
            float4 z4 = make_float4(0.f, 0.f, 0.f, 0.f);
#pragma unroll
            for (int u = 0; u < 8; u++) {
                float4 f0 = valid ? ap[u * 2]     : z4;
                float4 f1 = valid ? ap[u * 2 + 1] : z4;
                float fs[8] = {f0.x, f0.y, f0.z, f0.w, f1.x, f1.y, f1.z, f1.w};
                union { __nv_bfloat16 b[8]; uint4 v; } hi;
                union { __nv_bfloat16 b[8]; uint4 v; } lo;
#pragma unroll
                for (int j = 0; j < 8; j++) {
                    __nv_bfloat16 hb = __float2bfloat16(fs[j]);
                    hi.b[j] = hb;
                    lo.b[j] = __float2bfloat16(fs[j] - __bfloat162float(hb));
                }
                uint32_t off = (uint32_t)(r * 272 + half * 128 + u * 16);
                *reinterpret_cast<uint4*>(smem + SA_HI + off) = hi.v;
                *reinterpret_cast<uint4*>(smem + SA_LO + off) = lo.v;
            }
        }
        // ---- B chunk: global bf16 image -> smem (re-strided to 136) ----
        {
            const unsigned char* ch = Bimg + (size_t)(blockIdx.x * KB + kc) * 65536;
            const uint4* shi = reinterpret_cast<const uint4*>(ch + (size_t)r * 256 + half * 128);
            const uint4* slo = reinterpret_cast<const uint4*>(ch + 32768 + (size_t)r * 256 + half * 128);
            uint32_t off = (uint32_t)(r * 272 + half * 128);
            uint4* dhi = reinterpret_cast<uint4*>(smem + SB_HI + off);
            uint4* dlo = reinterpret_cast<uint4*>(smem + SB_LO + off);
#pragma unroll
            for (int u = 0; u < 8; u++) {
                dhi[u] = shi[u];
                dlo[u] = slo[u];
            }
        }
        __syncthreads();

        // ---- mma over 8 k16 steps ----
        uint32_t a_row = (uint32_t)(wm * 32 + (lane & 15));
        uint32_t a_cb  = (uint32_t)((lane >> 4) * 16);          // byte offset of k-col
        uint32_t b_n   = (uint32_t)(wn * 64 + ((lane >> 4) << 3) + (lane & 7));
        uint32_t b_cb  = (uint32_t)(((lane >> 3) & 1) * 16);    // byte offset of k-col
#pragma unroll
        for (int ks = 0; ks < 8; ks++) {
            uint32_t kb = (uint32_t)(ks * 32);  // k-step byte offset
            uint32_t Ahi0[4], Ahi1[4], Alo0[4], Alo1[4];
            ldsm_x4(sb + SA_HI + a_row * 272 + kb + a_cb, Ahi0);
            ldsm_x4(sb + SA_HI + (a_row + 16) * 272 + kb + a_cb, Ahi1);
            ldsm_x4(sb + SA_LO + a_row * 272 + kb + a_cb, Alo0);
            ldsm_x4(sb + SA_LO + (a_row + 16) * 272 + kb + a_cb, Alo1);
#pragma unroll
            for (int nj = 0; nj < 4; nj++) {
                uint32_t bh[4], bl[4];
                uint32_t baddr = (b_n + nj * 16) * 272 + kb + b_cb;
                ldsm_x4(sb + SB_HI + baddr, bh);
                ldsm_x4(sb + SB_LO + baddr, bl);
                // mi = 0
                mma_bf16(acc[0][2 * nj],     Ahi0, bh[0], bh[1]);
                mma_bf16(acc[0][2 * nj],     Ahi0, bl[0], bl[1]);
                mma_bf16(acc[0][2 * nj],     Alo0, bh[0], bh[1]);
                mma_bf16(acc[0][2 * nj + 1], Ahi0, bh[2], bh[3]);
                mma_bf16(acc[0][2 * nj + 1], Ahi0, bl[2], bl[3]);
                mma_bf16(acc[0][2 * nj + 1], Alo0, bh[2], bh[3]);
                // mi = 1
                mma_bf16(acc[1][2 * nj],     Ahi1, bh[0], bh[1]);
                mma_bf16(acc[1][2 * nj],     Ahi1, bl[0], bl[1]);
                mma_bf16(acc[1][2 * nj],     Alo1, bh[0], bh[1]);
                mma_bf16(acc[1][2 * nj + 1], Ahi1, bh[2], bh[3]);
                mma_bf16(acc[1][2 * nj + 1], Ahi1, bl[2], bl[3]);
                mma_bf16(acc[1][2 * nj + 1], Alo1, bh[2], bh[3]);
            }
        }
    }

    // ---- epilogue: direct stores ----
    int lrow = lane >> 2;
    int lcol = (lane & 3) * 2;
#pragma unroll
    for (int mi = 0; mi < 2; mi++) {
        int row0 = bm + wm * 32 + mi * 16 + lrow;
#pragma unroll
        for (int ni = 0; ni < 8; ni++) {
            int col = bn + wn * 64 + ni * 8 + lcol;
            float b0 = 0.f, b1 = 0.f;
            if (bias) {
                b0 = __ldg(bias + (col - bn));
                b1 = __ldg(bias + (col - bn) + 1);
            }
            if (row0 < M) {
                float2 v = make_float2(acc[mi][ni][0] + b0, acc[mi][ni][1] + b1);
                *reinterpret_cast<float2*>(C + (size_t)row0 * ldc + col) = v;
            }
            if (row0 + 8 < M) {
                float2 v = make_float2(acc[mi][ni][2] + b0, acc[mi][ni][3] + b1);
                *reinterpret_cast<float2*>(C + (size_t)(row0 + 8) * ldc + col) = v;
            }
        }
    }
}

// ---------------- layer epilogue ----------------
// h = rrelu( (Sagg+EW)/max(cnt,1) + (cnt>0)*bn + Tb + bl )
__global__ void layer_epi(const float* __restrict__ Sagg,
                          const float* __restrict__ EW,   // ld 256
                          const float* __restrict__ Tb,   // ld 256
                          const float* __restrict__ cnt,
                          const float* __restrict__ bn,
                          const float* __restrict__ bl,
                          float* __restrict__ hcat, int col_off) {
    int idx = blockIdx.x * blockDim.x + threadIdx.x;
    if (idx >= ND) return;
    int node = idx >> 7;
    int c    = idx & (D - 1);
    float cn  = cnt[node];
    float inv = 1.0f / fmaxf(cn, 1.0f);
    float pre = (Sagg[idx] + EW[(size_t)node * 256 + c]) * inv
              + (cn > 0.f ? __ldg(bn + c) : 0.f)
              + Tb[(size_t)node * 256 + c] + __ldg(bl + c);
    hcat[(size_t)node * 256 + col_off + c] = rrelu_f(pre);
}

// ---------------- launch ----------------
extern "C" void kernel_launch(void* const* d_in, const int* in_sizes, int n_in,
                              void* d_out, int out_size) {
    const float* x   = (const float*)d_in[0];
    const float* e   = (const float*)d_in[1];
    const int*   src = (const int*)d_in[2];
    const int*   dst = (const int*)d_in[3];
    const float* Wn0 = (const float*)d_in[4];
    const float* bn0 = (const float*)d_in[5];
    const float* Wl0 = (const float*)d_in[6];
    const float* bl0 = (const float*)d_in[7];
    const float* Wn1 = (const float*)d_in[8];
    const float* bn1 = (const float*)d_in[9];
    const float* Wl1 = (const float*)d_in[10];
    const float* bl1 = (const float*)d_in[11];
    const float* Wo  = (const float*)d_in[12];
    const float* bo  = (const float*)d_in[13];
    float* out = (float*)d_out;

    float* S = nullptr;
    cudaGetSymbolAddress((void**)&S, g_scratch);
    unsigned char* BI = nullptr;
    cudaGetSymbolAddress((void**)&BI, g_bimg);

    float* Eagg  = S + OFF_EAGG;
    float* Sagg0 = S + OFF_SAGG0;
    float* Sagg1 = S + OFF_SAGG1;
    float* cnt   = S + OFF_CNT;
    float* P0    = S + OFF_P0;
    float* PE    = S + OFF_PE;
    float* P1    = S + OFF_P1;
    float* HCAT  = S + OFF_HCAT;

    cudaFuncSetAttribute(gemm_mma,
                         cudaFuncAttributeMaxDynamicSharedMemorySize, SM_TOTAL);

    const int MT = (NN + 127) / 128;  // 391 m-tiles
    const int SCT = (NE * 32 + 255) / 256;

    // 0. weight images
    prep_B<<<8, 128>>>(Wn0, Wl0, Wn1, Wl1, Wo, BI);

    // 1. zero accumulators
    zero_kernel<<<(ZERO_N / 4 + 255) / 256, 256>>>((float4*)S, ZERO_N / 4);

    // 2. edge scatter + degree
    scatter_edges<<<SCT, 256>>>(e, dst, Eagg, cnt);

    // 3. G1: x @ [Wn0u | Wl0] -> P0
    gemm_mma<<<dim3(2, MT), 256, SM_TOTAL>>>(x, D, BI + 0 * 65536, 1, P0, 256, nullptr, NN);
    // 4. G2: Eagg @ [Wn0e | Wn1e] -> PE
    gemm_mma<<<dim3(2, MT), 256, SM_TOTAL>>>(Eagg, D, BI + 2 * 65536, 1, PE, 256, nullptr, NN);

    // 5. layer 0 scatter + epilogue
    scatter_T<<<SCT, 256>>>(P0, 256, src, dst, Sagg0);
    layer_epi<<<(ND + 255) / 256, 256>>>(Sagg0, PE, P0 + 128, cnt, bn0, bl0, HCAT, 0);

    // 6. G3: h1 @ [Wn1u | Wl1] -> P1  (A = HCAT cols 0-127, lda 256)
    gemm_mma<<<dim3(2, MT), 256, SM_TOTAL>>>(HCAT, 256, BI + 4 * 65536, 1, P1, 256, nullptr, NN);

    // 7. layer 1 scatter + epilogue
    scatter_T<<<SCT, 256>>>(P1, 256, src, dst, Sagg1);
    layer_epi<<<(ND + 255) / 256, 256>>>(Sagg1, PE + 128, P1 + 128, cnt, bn1, bl1, HCAT, D);

    // 8. G4: out = HCAT @ Wo + bo  (K=256 internal loop)
    gemm_mma<<<dim3(1, MT), 256, SM_TOTAL>>>(HCAT, 256, BI + 6 * 65536, 2, out, 128, bo, NN);
}

// round 5
// speedup vs baseline: 1.3300x; 1.0295x over previous
#include <cuda_runtime.h>
#include <cuda_bf16.h>
#include <cstdint>

#define NN 50000
#define NE 800000
#define D  128

static __device__ __forceinline__ float rrelu_f(float x) {
    const float SLOPE = (1.0f/8.0f + 1.0f/3.0f) * 0.5f;
    return x >= 0.0f ? x : x * SLOPE;
}

// ---------------- scratch layout (floats) ----------------
#define ND        (NN * D)                 // 6,400,000
#define OFF_EAGG  0
#define OFF_SAGG0 (ND)
#define OFF_SAGG1 (2 * ND)
#define OFF_CNT   (3 * ND)                 // 50048 slots
#define ZERO_N    (3 * ND + 50048)
#define OFF_P0    (ZERO_N)                 // 50k x 256: [T0A | T0B]
#define OFF_PE    (OFF_P0 + 2 * ND)        // 50k x 256: [EW0 | EW1]
#define OFF_P1    (OFF_PE + 2 * ND)        // 50k x 256: [T1A | T1B]
#define OFF_HCAT  (OFF_P1 + 2 * ND)        // 50k x 256
#define SCRATCH_N (OFF_HCAT + 2 * ND)

__device__ float g_scratch[SCRATCH_N];

// bf16 weight images: 8 chunks x 64KB. Chunk = hi[128][128] bf16 (Bt layout
// [n][k], row stride 256B) then lo[128][128]. Chunk order:
// 0:Wn0u 1:Wl0 2:Wn0e 3:Wn1e 4:Wn1u 5:Wl1 6:Wo[0:128] 7:Wo[128:256]
__device__ __align__(16) unsigned char g_bimg[8 * 65536];

// ---------------- PTX helpers ----------------
__device__ __forceinline__ uint32_t smem_u32(const void* p) {
    uint32_t a;
    asm("{ .reg .u64 t; cvta.to.shared.u64 t, %1; cvt.u32.u64 %0, t; }" : "=r"(a) : "l"(p));
    return a;
}

__device__ __forceinline__ void ldsm_x4(uint32_t addr, uint32_t* r) {
    asm volatile("ldmatrix.sync.aligned.m8n8.x4.shared.b16 {%0,%1,%2,%3}, [%4];"
                 : "=r"(r[0]), "=r"(r[1]), "=r"(r[2]), "=r"(r[3]) : "r"(addr));
}

__device__ __forceinline__ void mma_bf16(float* c, const uint32_t* a,
                                         uint32_t b0, uint32_t b1) {
    asm volatile("mma.sync.aligned.m16n8k16.row.col.f32.bf16.bf16.f32 "
                 "{%0,%1,%2,%3}, {%4,%5,%6,%7}, {%8,%9}, {%0,%1,%2,%3};"
                 : "+f"(c[0]), "+f"(c[1]), "+f"(c[2]), "+f"(c[3])
                 : "r"(a[0]), "r"(a[1]), "r"(a[2]), "r"(a[3]), "r"(b0), "r"(b1));
}

__device__ __forceinline__ void red_add_v4(float* p, float4 v) {
    asm volatile("red.global.add.v4.f32 [%0], {%1,%2,%3,%4};"
                 :: "l"(p), "f"(v.x), "f"(v.y), "f"(v.z), "f"(v.w)
                 : "memory");
}

// ---------------- zero ----------------
__global__ void zero_kernel(float4* p, int n4) {
    int i = blockIdx.x * blockDim.x + threadIdx.x;
    if (i < n4) p[i] = make_float4(0.f, 0.f, 0.f, 0.f);
}

// ---------------- edge-feature scatter + degree ----------------
__global__ void scatter_edges(const float* __restrict__ e,
                              const int* __restrict__ dst,
                              float* __restrict__ Eagg,
                              float* __restrict__ cnt) {
    int w    = (blockIdx.x * blockDim.x + threadIdx.x) >> 5;
    int lane = threadIdx.x & 31;
    if (w >= NE) return;
    int d = __ldg(dst + w);
    float4 v = *reinterpret_cast<const float4*>(e + (size_t)w * D + lane * 4);
    red_add_v4(Eagg + (size_t)d * D + lane * 4, v);
    if (lane == 0)
        atomicAdd(cnt + d, 1.0f);
}

// ---------------- projected-node scatter (T has leading dim ld) ----------------
__global__ void scatter_T(const float* __restrict__ T, int ld,
                          const int* __restrict__ src,
                          const int* __restrict__ dst,
                          float* __restrict__ Sagg) {
    int w    = (blockIdx.x * blockDim.x + threadIdx.x) >> 5;
    int lane = threadIdx.x & 31;
    if (w >= NE) return;
    int s = __ldg(src + w);
    int d = __ldg(dst + w);
    float4 v = *reinterpret_cast<const float4*>(T + (size_t)s * ld + lane * 4);
    red_add_v4(Sagg + (size_t)d * D + lane * 4, v);
}

// ---------------- weight image prep ----------------
__global__ void prep_B(const float* __restrict__ Wn0, const float* __restrict__ Wl0,
                       const float* __restrict__ Wn1, const float* __restrict__ Wl1,
                       const float* __restrict__ Wo, unsigned char* __restrict__ img) {
    int ci = blockIdx.x;
    const float* W;
    switch (ci) {
        case 0: W = Wn0; break;
        case 1: W = Wl0; break;
        case 2: W = Wn0 + 128 * 128; break;
        case 3: W = Wn1 + 128 * 128; break;
        case 4: W = Wn1; break;
        case 5: W = Wl1; break;
        case 6: W = Wo; break;
        default: W = Wo + 128 * 128; break;
    }
    unsigned char* hi_img = img + ci * 65536;
    unsigned char* lo_img = hi_img + 32768;

    __shared__ float sw[64][129];
    int t = threadIdx.x;  // 128
    for (int kt = 0; kt < 2; kt++) {
        for (int i = t; i < 64 * 128; i += 128)
            sw[i >> 7][i & 127] = W[kt * 64 * 128 + i];
        __syncthreads();
        int n = t;
#pragma unroll
        for (int u = 0; u < 8; u++) {
            union { __nv_bfloat16 h[8]; uint4 v; } hi;
            union { __nv_bfloat16 h[8]; uint4 v; } lo;
#pragma unroll
            for (int j = 0; j < 8; j++) {
                float f = sw[u * 8 + j][n];
                __nv_bfloat16 hb = __float2bfloat16(f);
                hi.h[j] = hb;
                lo.h[j] = __float2bfloat16(f - __bfloat162float(hb));
            }
            uint32_t off = (uint32_t)(n * 256 + kt * 128 + u * 16);
            *reinterpret_cast<uint4*>(hi_img + off) = hi.v;
            *reinterpret_cast<uint4*>(lo_img + off) = lo.v;
        }
        __syncthreads();
    }
}

// ---------------- HMMA bf16x3 GEMM: 128x64 tile, K=128 ----------------
// C[:, bx*64 : bx*64+64] (+)= A[:, 0:128] @ chunk(bx>>1)[rows (bx&1)*64 ..]
// smem: A hi/lo [128][136] bf16, B hi/lo [64][136] bf16 -> 104448 B, 2 CTAs/SM
#define SA_HI 0
#define SA_LO 34816
#define SB_HI 69632
#define SB_LO 87040
#define SM_TOTAL 104448

__global__ __launch_bounds__(256, 2)
void gemm_mma(const float* __restrict__ A, int lda,
              const unsigned char* __restrict__ Bimg,
              float* __restrict__ C, int ldc,
              const float* __restrict__ bias, int accumulate, int M) {
    extern __shared__ unsigned char smem[];
    uint32_t sb = smem_u32(smem);
    int tid  = threadIdx.x;
    int lane = tid & 31;
    int wid  = tid >> 5;
    int wm   = wid & 3;       // 4 m-tiles of 32 rows
    int wn   = wid >> 2;      // 2 n-tiles of 32 cols
    int bm   = blockIdx.y * 128;

    float acc[2][4][4];
#pragma unroll
    for (int mi = 0; mi < 2; mi++)
#pragma unroll
        for (int ni = 0; ni < 4; ni++)
#pragma unroll
            for (int q = 0; q < 4; q++) acc[mi][ni][q] = 0.f;

    // ---- A: global f32 -> smem bf16 hi/lo ----
    {
        int r    = tid >> 1;
        int half = tid & 1;
        bool valid = (bm + r) < M;
        const float4* ap = reinterpret_cast<const float4*>(
            A + (size_t)(bm + r) * lda + half * 64);
        float4 z4 = make_float4(0.f, 0.f, 0.f, 0.f);
#pragma unroll
        for (int u = 0; u < 8; u++) {
            float4 f0 = valid ? ap[u * 2]     : z4;
            float4 f1 = valid ? ap[u * 2 + 1] : z4;
            float fs[8] = {f0.x, f0.y, f0.z, f0.w, f1.x, f1.y, f1.z, f1.w};
            union { __nv_bfloat16 b[8]; uint4 v; } hi;
            union { __nv_bfloat16 b[8]; uint4 v; } lo;
#pragma unroll
            for (int j = 0; j < 8; j++) {
                __nv_bfloat16 hb = __float2bfloat16(fs[j]);
                hi.b[j] = hb;
                lo.b[j] = __float2bfloat16(fs[j] - __bfloat162float(hb));
            }
            uint32_t off = (uint32_t)(r * 272 + half * 128 + u * 16);
            *reinterpret_cast<uint4*>(smem + SA_HI + off) = hi.v;
            *reinterpret_cast<uint4*>(smem + SA_LO + off) = lo.v;
        }
    }
    // ---- B: bf16 image rows [(bx&1)*64, +64) -> smem (stride 272) ----
    {
        const unsigned char* ch = Bimg + (size_t)(blockIdx.x >> 1) * 65536
                                + (size_t)(blockIdx.x & 1) * 64 * 256;
#pragma unroll
        for (int i = 0; i < 4; i++) {
            int linear = tid + i * 256;        // 0..1023
            int row = linear >> 4;             // 0..63
            int c16 = linear & 15;
            uint32_t soff = (uint32_t)(row * 256 + c16 * 16);
            uint32_t doff = (uint32_t)(row * 272 + c16 * 16);
            *reinterpret_cast<uint4*>(smem + SB_HI + doff) =
                *reinterpret_cast<const uint4*>(ch + soff);
            *reinterpret_cast<uint4*>(smem + SB_LO + doff) =
                *reinterpret_cast<const uint4*>(ch + 32768 + soff);
        }
    }
    __syncthreads();

    // ---- MMA over 8 k16 steps ----
    uint32_t a_row = (uint32_t)(wm * 32 + (lane & 15));
    uint32_t a_cb  = (uint32_t)((lane >> 4) * 16);
    uint32_t b_n   = (uint32_t)(wn * 32 + ((lane >> 4) << 3) + (lane & 7));
    uint32_t b_cb  = (uint32_t)(((lane >> 3) & 1) * 16);
#pragma unroll
    for (int ks = 0; ks < 8; ks++) {
        uint32_t kb = (uint32_t)(ks * 32);
        uint32_t Ahi0[4], Ahi1[4], Alo0[4], Alo1[4];
        ldsm_x4(sb + SA_HI + a_row * 272 + kb + a_cb, Ahi0);
        ldsm_x4(sb + SA_HI + (a_row + 16) * 272 + kb + a_cb, Ahi1);
        ldsm_x4(sb + SA_LO + a_row * 272 + kb + a_cb, Alo0);
        ldsm_x4(sb + SA_LO + (a_row + 16) * 272 + kb + a_cb, Alo1);
#pragma unroll
        for (int nj = 0; nj < 2; nj++) {
            uint32_t bh[4], bl[4];
            uint32_t baddr = (b_n + nj * 16) * 272 + kb + b_cb;
            ldsm_x4(sb + SB_HI + baddr, bh);
            ldsm_x4(sb + SB_LO + baddr, bl);
            mma_bf16(acc[0][2 * nj],     Ahi0, bh[0], bh[1]);
            mma_bf16(acc[0][2 * nj],     Ahi0, bl[0], bl[1]);
            mma_bf16(acc[0][2 * nj],     Alo0, bh[0], bh[1]);
            mma_bf16(acc[0][2 * nj + 1], Ahi0, bh[2], bh[3]);
            mma_bf16(acc[0][2 * nj + 1], Ahi0, bl[2], bl[3]);
            mma_bf16(acc[0][2 * nj + 1], Alo0, bh[2], bh[3]);
            mma_bf16(acc[1][2 * nj],     Ahi1, bh[0], bh[1]);
            mma_bf16(acc[1][2 * nj],     Ahi1, bl[0], bl[1]);
            mma_bf16(acc[1][2 * nj],     Alo1, bh[0], bh[1]);
            mma_bf16(acc[1][2 * nj + 1], Ahi1, bh[2], bh[3]);
            mma_bf16(acc[1][2 * nj + 1], Ahi1, bl[2], bl[3]);
            mma_bf16(acc[1][2 * nj + 1], Alo1, bh[2], bh[3]);
        }
    }

    // ---- epilogue ----
    int lrow = lane >> 2;
    int lcol = (lane & 3) * 2;
#pragma unroll
    for (int mi = 0; mi < 2; mi++) {
        int row0 = bm + wm * 32 + mi * 16 + lrow;
#pragma unroll
        for (int ni = 0; ni < 4; ni++) {
            int gcol = blockIdx.x * 64 + wn * 32 + ni * 8 + lcol;
            float b0 = 0.f, b1 = 0.f;
            if (bias) {
                b0 = __ldg(bias + gcol);
                b1 = __ldg(bias + gcol + 1);
            }
            if (row0 < M) {
                float* cp = C + (size_t)row0 * ldc + gcol;
                float2 v = make_float2(acc[mi][ni][0] + b0, acc[mi][ni][1] + b1);
                if (accumulate) { float2 o = *reinterpret_cast<float2*>(cp); v.x += o.x; v.y += o.y; }
                *reinterpret_cast<float2*>(cp) = v;
            }
            if (row0 + 8 < M) {
                float* cp = C + (size_t)(row0 + 8) * ldc + gcol;
                float2 v = make_float2(acc[mi][ni][2] + b0, acc[mi][ni][3] + b1);
                if (accumulate) { float2 o = *reinterpret_cast<float2*>(cp); v.x += o.x; v.y += o.y; }
                *reinterpret_cast<float2*>(cp) = v;
            }
        }
    }
}

// ---------------- layer epilogue ----------------
__global__ void layer_epi(const float* __restrict__ Sagg,
                          const float* __restrict__ EW,   // ld 256
                          const float* __restrict__ Tb,   // ld 256
                          const float* __restrict__ cnt,
                          const float* __restrict__ bn,
                          const float* __restrict__ bl,
                          float* __restrict__ hcat, int col_off) {
    int idx = blockIdx.x * blockDim.x + threadIdx.x;
    if (idx >= ND) return;
    int node = idx >> 7;
    int c    = idx & (D - 1);
    float cn  = cnt[node];
    float inv = 1.0f / fmaxf(cn, 1.0f);
    float pre = (Sagg[idx] + EW[(size_t)node * 256 + c]) * inv
              + (cn > 0.f ? __ldg(bn + c) : 0.f)
              + Tb[(size_t)node * 256 + c] + __ldg(bl + c);
    hcat[(size_t)node * 256 + col_off + c] = rrelu_f(pre);
}

// ---------------- launch ----------------
extern "C" void kernel_launch(void* const* d_in, const int* in_sizes, int n_in,
                              void* d_out, int out_size) {
    const float* x   = (const float*)d_in[0];
    const float* e   = (const float*)d_in[1];
    const int*   src = (const int*)d_in[2];
    const int*   dst = (const int*)d_in[3];
    const float* Wn0 = (const float*)d_in[4];
    const float* bn0 = (const float*)d_in[5];
    const float* Wl0 = (const float*)d_in[6];
    const float* bl0 = (const float*)d_in[7];
    const float* Wn1 = (const float*)d_in[8];
    const float* bn1 = (const float*)d_in[9];
    const float* Wl1 = (const float*)d_in[10];
    const float* bl1 = (const float*)d_in[11];
    const float* Wo  = (const float*)d_in[12];
    const float* bo  = (const float*)d_in[13];
    float* out = (float*)d_out;

    float* S = nullptr;
    cudaGetSymbolAddress((void**)&S, g_scratch);
    unsigned char* BI = nullptr;
    cudaGetSymbolAddress((void**)&BI, g_bimg);

    float* Eagg  = S + OFF_EAGG;
    float* Sagg0 = S + OFF_SAGG0;
    float* Sagg1 = S + OFF_SAGG1;
    float* cnt   = S + OFF_CNT;
    float* P0    = S + OFF_P0;
    float* PE    = S + OFF_PE;
    float* P1    = S + OFF_P1;
    float* HCAT  = S + OFF_HCAT;

    static cudaStream_t s1 = nullptr;
    static cudaEvent_t evRoot, evSE, evG1, evST0, evE0, evG4a;
    if (!s1) {
        cudaStreamCreateWithFlags(&s1, cudaStreamNonBlocking);
        cudaEventCreateWithFlags(&evRoot, cudaEventDisableTiming);
        cudaEventCreateWithFlags(&evSE,  cudaEventDisableTiming);
        cudaEventCreateWithFlags(&evG1,  cudaEventDisableTiming);
        cudaEventCreateWithFlags(&evST0, cudaEventDisableTiming);
        cudaEventCreateWithFlags(&evE0,  cudaEventDisableTiming);
        cudaEventCreateWithFlags(&evG4a, cudaEventDisableTiming);
    }

    cudaFuncSetAttribute(gemm_mma,
                         cudaFuncAttributeMaxDynamicSharedMemorySize, SM_TOTAL);

    const int MT  = (NN + 127) / 128;        // 391 m-tiles
    const int SCT = (NE * 32 + 255) / 256;
    const dim3 G4T(4, MT), G2T(2, MT);
    const int EPB = (ND + 255) / 256;

    // fork root: s1 must branch FROM the capture-origin stream
    cudaEventRecord(evRoot, 0);
    cudaStreamWaitEvent(s1, evRoot, 0);

    // s1: zero accumulators -> edge scatter (+degree)
    zero_kernel<<<(ZERO_N / 4 + 255) / 256, 256, 0, s1>>>((float4*)S, ZERO_N / 4);
    scatter_edges<<<SCT, 256, 0, s1>>>(e, dst, Eagg, cnt);
    cudaEventRecord(evSE, s1);

    // s0: weight images then G1: x @ [Wn0u | Wl0] -> P0
    prep_B<<<8, 128>>>(Wn0, Wl0, Wn1, Wl1, Wo, BI);
    gemm_mma<<<G4T, 256, SM_TOTAL>>>(x, D, BI + 0 * 65536, P0, 256, nullptr, 0, NN);
    cudaEventRecord(evG1, 0);

    // s1: scatter_T0 (needs P0 + zero)
    cudaStreamWaitEvent(s1, evG1, 0);
    scatter_T<<<SCT, 256, 0, s1>>>(P0, 256, src, dst, Sagg0);
    cudaEventRecord(evST0, s1);

    // s0: G2: Eagg @ [Wn0e | Wn1e] -> PE  (needs scatter_edges)
    cudaStreamWaitEvent(0, evSE, 0);
    gemm_mma<<<G4T, 256, SM_TOTAL>>>(Eagg, D, BI + 2 * 65536, PE, 256, nullptr, 0, NN);

    // s0: epi0 (needs PE, Sagg0, cnt)
    cudaStreamWaitEvent(0, evST0, 0);
    layer_epi<<<EPB, 256>>>(Sagg0, PE, P0 + 128, cnt, bn0, bl0, HCAT, 0);
    cudaEventRecord(evE0, 0);

    // s0: G3: h1 @ [Wn1u | Wl1] -> P1
    gemm_mma<<<G4T, 256, SM_TOTAL>>>(HCAT, 256, BI + 4 * 65536, P1, 256, nullptr, 0, NN);

    // s1: G4a: out = h1 @ Wo_top + bo   (needs epi0)
    cudaStreamWaitEvent(s1, evE0, 0);
    gemm_mma<<<G2T, 256, SM_TOTAL, s1>>>(HCAT, 256, BI + 6 * 65536, out, 128, bo, 0, NN);
    cudaEventRecord(evG4a, s1);

    // s0: layer 1 scatter + epilogue
    scatter_T<<<SCT, 256>>>(P1, 256, src, dst, Sagg1);
    layer_epi<<<EPB, 256>>>(Sagg1, PE + 128, P1 + 128, cnt, bn1, bl1, HCAT, D);

    // s0: G4b: out += h2 @ Wo_bot   (joins s1 branch back; needs G4a + epi1)
    cudaStreamWaitEvent(0, evG4a, 0);
    gemm_mma<<<G2T, 256, SM_TOTAL>>>(HCAT + 128, 256, BI + 7 * 65536, out, 128, nullptr, 1, NN);
}

// round 6
// speedup vs baseline: 1.7967x; 1.3509x over previous
#include <cuda_runtime.h>
#include <cuda_bf16.h>
#include <cstdint>

#define NN 50000
#define NE 800000
#define D  128

static __device__ __forceinline__ float rrelu_f(float x) {
    const float SLOPE = (1.0f/8.0f + 1.0f/3.0f) * 0.5f;
    return x >= 0.0f ? x : x * SLOPE;
}

// ---------------- scratch layout (floats) ----------------
#define ND        (NN * D)                 // 6,400,000
#define OFF_EAGG  0
#define OFF_P0    (ND)                     // 50k x 256: [T0A | T0B]
#define OFF_PE    (3 * ND)                 // 50k x 256: [EW0 | EW1]
#define OFF_P1    (5 * ND)                 // 50k x 256: [T1A | T1B]
#define OFF_HCAT  (7 * ND)                 // 50k x 256
#define OFF_INT   (9 * ND)                 // int area
// int offsets within int area
#define NI_HIST 0
#define NI_INCL 50176
#define NI_BLK  100352
#define NI_BOFF 100416
#define NI_RP   100480        // 50001 entries
#define NI_WP   150912
#define NI_PS   201088        // src[perm]  (800000)
#define NI_PE   1001088       // edge id perm (800000)
#define NI_TOTAL 1801088
#define SCRATCH_N (OFF_INT + NI_TOTAL)

__device__ float g_scratch[SCRATCH_N];

// bf16 weight images: 8 chunks x 64KB. Chunk = hi[128][128] bf16 (Bt layout
// [n][k], row stride 256B) then lo[128][128]. Chunk order:
// 0:Wn0u 1:Wl0 2:Wn0e 3:Wn1e 4:Wn1u 5:Wl1 6:Wo[0:128] 7:Wo[128:256]
__device__ __align__(16) unsigned char g_bimg[8 * 65536];

// ---------------- PTX helpers ----------------
__device__ __forceinline__ uint32_t smem_u32(const void* p) {
    uint32_t a;
    asm("{ .reg .u64 t; cvta.to.shared.u64 t, %1; cvt.u32.u64 %0, t; }" : "=r"(a) : "l"(p));
    return a;
}

__device__ __forceinline__ void ldsm_x4(uint32_t addr, uint32_t* r) {
    asm volatile("ldmatrix.sync.aligned.m8n8.x4.shared.b16 {%0,%1,%2,%3}, [%4];"
                 : "=r"(r[0]), "=r"(r[1]), "=r"(r[2]), "=r"(r[3]) : "r"(addr));
}

__device__ __forceinline__ void mma_bf16(float* c, const uint32_t* a,
                                         uint32_t b0, uint32_t b1) {
    asm volatile("mma.sync.aligned.m16n8k16.row.col.f32.bf16.bf16.f32 "
                 "{%0,%1,%2,%3}, {%4,%5,%6,%7}, {%8,%9}, {%0,%1,%2,%3};"
                 : "+f"(c[0]), "+f"(c[1]), "+f"(c[2]), "+f"(c[3])
                 : "r"(a[0]), "r"(a[1]), "r"(a[2]), "r"(a[3]), "r"(b0), "r"(b1));
}

// ---------------- CSR build ----------------
__global__ void zero_hist(int* hist) {
    int i = blockIdx.x * blockDim.x + threadIdx.x;
    if (i < NN) hist[i] = 0;
}

__global__ void hist_k(const int* __restrict__ dst, int* __restrict__ hist) {
    int i = blockIdx.x * blockDim.x + threadIdx.x;
    if (i < NE) atomicAdd(hist + __ldg(dst + i), 1);
}

// block-level inclusive scan (1024/block, 49 blocks)
__global__ void scanA(const int* __restrict__ hist, int* __restrict__ incl,
                      int* __restrict__ blk) {
    __shared__ int s[1024];
    int t = threadIdx.x;
    int i = blockIdx.x * 1024 + t;
    int v = (i < NN) ? hist[i] : 0;
    s[t] = v;
    __syncthreads();
#pragma unroll
    for (int off = 1; off < 1024; off <<= 1) {
        int add = (t >= off) ? s[t - off] : 0;
        __syncthreads();
        s[t] += add;
        __syncthreads();
    }
    incl[i] = s[t];
    if (t == 1023) blk[blockIdx.x] = s[t];
}

__global__ void scanB(const int* __restrict__ blk, int* __restrict__ boff) {
    __shared__ int s[64];
    int t = threadIdx.x;
    if (t < 49) s[t] = blk[t];
    __syncthreads();
    if (t == 0) {
        int run = 0;
        for (int b = 0; b < 49; b++) { int v = s[b]; s[b] = run; run += v; }
    }
    __syncthreads();
    if (t < 49) boff[t] = s[t];
}

__global__ void scanC(const int* __restrict__ incl, const int* __restrict__ boff,
                      const int* __restrict__ hist,
                      int* __restrict__ rp, int* __restrict__ wp) {
    int t = threadIdx.x;
    int i = blockIdx.x * 1024 + t;
    if (i < NN) {
        int inc = incl[i] + boff[blockIdx.x];
        rp[i + 1] = inc;
        wp[i] = inc - hist[i];
    }
    if (i == 0) rp[0] = 0;
}

__global__ void permute_k(const int* __restrict__ src, const int* __restrict__ dst,
                          int* __restrict__ wp,
                          int* __restrict__ ps, int* __restrict__ pe) {
    int i = blockIdx.x * blockDim.x + threadIdx.x;
    if (i >= NE) return;
    int d = __ldg(dst + i);
    int pos = atomicAdd(wp + d, 1);
    ps[pos] = __ldg(src + i);
    pe[pos] = i;
}

// ---------------- CSR gathers ----------------
// Eagg[n] = sum over edges into n of e[eid]
__global__ void gather_e(const float* __restrict__ e,
                         const int* __restrict__ rp,
                         const int* __restrict__ pe,
                         float* __restrict__ Eagg) {
    int w    = (blockIdx.x * blockDim.x + threadIdx.x) >> 5;
    int lane = threadIdx.x & 31;
    if (w >= NN) return;
    int beg = __ldg(rp + w), end = __ldg(rp + w + 1);
    float4 acc = make_float4(0.f, 0.f, 0.f, 0.f);
    for (int j = beg; j < end; j += 32) {
        int m = min(32, end - j);
        int eid = (lane < m) ? __ldg(pe + j + lane) : 0;
        for (int t = 0; t < m; t++) {
            int et = __shfl_sync(0xffffffffu, eid, t);
            float4 v = *reinterpret_cast<const float4*>(e + (size_t)et * D + lane * 4);
            acc.x += v.x; acc.y += v.y; acc.z += v.z; acc.w += v.w;
        }
    }
    *reinterpret_cast<float4*>(Eagg + (size_t)w * D + lane * 4) = acc;
}

// fused gather + layer epilogue:
// h = rrelu( (sum T[src] + EW[n]) / max(cnt,1) + (cnt>0)*bn + Tb[n] + bl )
__global__ void gather_epi(const float* __restrict__ T,    // ld 256, cols 0-127
                           const float* __restrict__ Tb,   // ld 256 (self-loop proj)
                           const float* __restrict__ EW,   // ld 256
                           const int* __restrict__ rp,
                           const int* __restrict__ ps,
                           const float* __restrict__ bn,
                           const float* __restrict__ bl,
                           float* __restrict__ hc) {       // ld 256
    int w    = (blockIdx.x * blockDim.x + threadIdx.x) >> 5;
    int lane = threadIdx.x & 31;
    if (w >= NN) return;
    int beg = __ldg(rp + w), end = __ldg(rp + w + 1);
    float4 acc = make_float4(0.f, 0.f, 0.f, 0.f);
    for (int j = beg; j < end; j += 32) {
        int m = min(32, end - j);
        int sidx = (lane < m) ? __ldg(ps + j + lane) : 0;
        for (int t = 0; t < m; t++) {
            int s = __shfl_sync(0xffffffffu, sidx, t);
            float4 v = *reinterpret_cast<const float4*>(T + (size_t)s * 256 + lane * 4);
            acc.x += v.x; acc.y += v.y; acc.z += v.z; acc.w += v.w;
        }
    }
    int cn = end - beg;
    float inv = 1.0f / fmaxf((float)cn, 1.0f);
    float g = (cn > 0) ? 1.0f : 0.0f;
    float4 ew = *reinterpret_cast<const float4*>(EW + (size_t)w * 256 + lane * 4);
    float4 tb = *reinterpret_cast<const float4*>(Tb + (size_t)w * 256 + lane * 4);
    float4 b4 = *reinterpret_cast<const float4*>(bn + lane * 4);
    float4 l4 = *reinterpret_cast<const float4*>(bl + lane * 4);
    float4 o;
    o.x = rrelu_f((acc.x + ew.x) * inv + g * b4.x + tb.x + l4.x);
    o.y = rrelu_f((acc.y + ew.y) * inv + g * b4.y + tb.y + l4.y);
    o.z = rrelu_f((acc.z + ew.z) * inv + g * b4.z + tb.z + l4.z);
    o.w = rrelu_f((acc.w + ew.w) * inv + g * b4.w + tb.w + l4.w);
    *reinterpret_cast<float4*>(hc + (size_t)w * 256 + lane * 4) = o;
}

// ---------------- weight image prep ----------------
__global__ void prep_B(const float* __restrict__ Wn0, const float* __restrict__ Wl0,
                       const float* __restrict__ Wn1, const float* __restrict__ Wl1,
                       const float* __restrict__ Wo, unsigned char* __restrict__ img) {
    int ci = blockIdx.x;
    const float* W;
    switch (ci) {
        case 0: W = Wn0; break;
        case 1: W = Wl0; break;
        case 2: W = Wn0 + 128 * 128; break;
        case 3: W = Wn1 + 128 * 128; break;
        case 4: W = Wn1; break;
        case 5: W = Wl1; break;
        case 6: W = Wo; break;
        default: W = Wo + 128 * 128; break;
    }
    unsigned char* hi_img = img + ci * 65536;
    unsigned char* lo_img = hi_img + 32768;

    __shared__ float sw[64][129];
    int t = threadIdx.x;  // 128
    for (int kt = 0; kt < 2; kt++) {
        for (int i = t; i < 64 * 128; i += 128)
            sw[i >> 7][i & 127] = W[kt * 64 * 128 + i];
        __syncthreads();
        int n = t;
#pragma unroll
        for (int u = 0; u < 8; u++) {
            union { __nv_bfloat16 h[8]; uint4 v; } hi;
            union { __nv_bfloat16 h[8]; uint4 v; } lo;
#pragma unroll
            for (int j = 0; j < 8; j++) {
                float f = sw[u * 8 + j][n];
                __nv_bfloat16 hb = __float2bfloat16(f);
                hi.h[j] = hb;
                lo.h[j] = __float2bfloat16(f - __bfloat162float(hb));
            }
            uint32_t off = (uint32_t)(n * 256 + kt * 128 + u * 16);
            *reinterpret_cast<uint4*>(hi_img + off) = hi.v;
            *reinterpret_cast<uint4*>(lo_img + off) = lo.v;
        }
        __syncthreads();
    }
}

// ---------------- HMMA bf16x3 GEMM: 128x64 tile, K=128 ----------------
#define SA_HI 0
#define SA_LO 34816
#define SB_HI 69632
#define SB_LO 87040
#define SM_TOTAL 104448

__global__ __launch_bounds__(256, 2)
void gemm_mma(const float* __restrict__ A, int lda,
              const unsigned char* __restrict__ Bimg,
              float* __restrict__ C, int ldc,
              const float* __restrict__ bias, int accumulate, int M) {
    extern __shared__ unsigned char smem[];
    uint32_t sb = smem_u32(smem);
    int tid  = threadIdx.x;
    int lane = tid & 31;
    int wid  = tid >> 5;
    int wm   = wid & 3;
    int wn   = wid >> 2;
    int bm   = blockIdx.y * 128;

    float acc[2][4][4];
#pragma unroll
    for (int mi = 0; mi < 2; mi++)
#pragma unroll
        for (int ni = 0; ni < 4; ni++)
#pragma unroll
            for (int q = 0; q < 4; q++) acc[mi][ni][q] = 0.f;

    {
        int r    = tid >> 1;
        int half = tid & 1;
        bool valid = (bm + r) < M;
        const float4* ap = reinterpret_cast<const float4*>(
            A + (size_t)(bm + r) * lda + half * 64);
        float4 z4 = make_float4(0.f, 0.f, 0.f, 0.f);
#pragma unroll
        for (int u = 0; u < 8; u++) {
            float4 f0 = valid ? ap[u * 2]     : z4;
            float4 f1 = valid ? ap[u * 2 + 1] : z4;
            float fs[8] = {f0.x, f0.y, f0.z, f0.w, f1.x, f1.y, f1.z, f1.w};
            union { __nv_bfloat16 b[8]; uint4 v; } hi;
            union { __nv_bfloat16 b[8]; uint4 v; } lo;
#pragma unroll
            for (int j = 0; j < 8; j++) {
                __nv_bfloat16 hb = __float2bfloat16(fs[j]);
                hi.b[j] = hb;
                lo.b[j] = __float2bfloat16(fs[j] - __bfloat162float(hb));
            }
            uint32_t off = (uint32_t)(r * 272 + half * 128 + u * 16);
            *reinterpret_cast<uint4*>(smem + SA_HI + off) = hi.v;
            *reinterpret_cast<uint4*>(smem + SA_LO + off) = lo.v;
        }
    }
    {
        const unsigned char* ch = Bimg + (size_t)(blockIdx.x >> 1) * 65536
                                + (size_t)(blockIdx.x & 1) * 64 * 256;
#pragma unroll
        for (int i = 0; i < 4; i++) {
            int linear = tid + i * 256;
            int row = linear >> 4;
            int c16 = linear & 15;
            uint32_t soff = (uint32_t)(row * 256 + c16 * 16);
            uint32_t doff = (uint32_t)(row * 272 + c16 * 16);
            *reinterpret_cast<uint4*>(smem + SB_HI + doff) =
                *reinterpret_cast<const uint4*>(ch + soff);
            *reinterpret_cast<uint4*>(smem + SB_LO + doff) =
                *reinterpret_cast<const uint4*>(ch + 32768 + soff);
        }
    }
    __syncthreads();

    uint32_t a_row = (uint32_t)(wm * 32 + (lane & 15));
    uint32_t a_cb  = (uint32_t)((lane >> 4) * 16);
    uint32_t b_n   = (uint32_t)(wn * 32 + ((lane >> 4) << 3) + (lane & 7));
    uint32_t b_cb  = (uint32_t)(((lane >> 3) & 1) * 16);
#pragma unroll
    for (int ks = 0; ks < 8; ks++) {
        uint32_t kb = (uint32_t)(ks * 32);
        uint32_t Ahi0[4], Ahi1[4], Alo0[4], Alo1[4];
        ldsm_x4(sb + SA_HI + a_row * 272 + kb + a_cb, Ahi0);
        ldsm_x4(sb + SA_HI + (a_row + 16) * 272 + kb + a_cb, Ahi1);
        ldsm_x4(sb + SA_LO + a_row * 272 + kb + a_cb, Alo0);
        ldsm_x4(sb + SA_LO + (a_row + 16) * 272 + kb + a_cb, Alo1);
#pragma unroll
        for (int nj = 0; nj < 2; nj++) {
            uint32_t bh[4], bl[4];
            uint32_t baddr = (b_n + nj * 16) * 272 + kb + b_cb;
            ldsm_x4(sb + SB_HI + baddr, bh);
            ldsm_x4(sb + SB_LO + baddr, bl);
            mma_bf16(acc[0][2 * nj],     Ahi0, bh[0], bh[1]);
            mma_bf16(acc[0][2 * nj],     Ahi0, bl[0], bl[1]);
            mma_bf16(acc[0][2 * nj],     Alo0, bh[0], bh[1]);
            mma_bf16(acc[0][2 * nj + 1], Ahi0, bh[2], bh[3]);
            mma_bf16(acc[0][2 * nj + 1], Ahi0, bl[2], bl[3]);
            mma_bf16(acc[0][2 * nj + 1], Alo0, bh[2], bh[3]);
            mma_bf16(acc[1][2 * nj],     Ahi1, bh[0], bh[1]);
            mma_bf16(acc[1][2 * nj],     Ahi1, bl[0], bl[1]);
            mma_bf16(acc[1][2 * nj],     Alo1, bh[0], bh[1]);
            mma_bf16(acc[1][2 * nj + 1], Ahi1, bh[2], bh[3]);
            mma_bf16(acc[1][2 * nj + 1], Ahi1, bl[2], bl[3]);
            mma_bf16(acc[1][2 * nj + 1], Alo1, bh[2], bh[3]);
        }
    }

    int lrow = lane >> 2;
    int lcol = (lane & 3) * 2;
#pragma unroll
    for (int mi = 0; mi < 2; mi++) {
        int row0 = bm + wm * 32 + mi * 16 + lrow;
#pragma unroll
        for (int ni = 0; ni < 4; ni++) {
            int gcol = blockIdx.x * 64 + wn * 32 + ni * 8 + lcol;
            float b0 = 0.f, b1 = 0.f;
            if (bias) {
                b0 = __ldg(bias + gcol);
                b1 = __ldg(bias + gcol + 1);
            }
            if (row0 < M) {
                float* cp = C + (size_t)row0 * ldc + gcol;
                float2 v = make_float2(acc[mi][ni][0] + b0, acc[mi][ni][1] + b1);
                if (accumulate) { float2 o = *reinterpret_cast<float2*>(cp); v.x += o.x; v.y += o.y; }
                *reinterpret_cast<float2*>(cp) = v;
            }
            if (row0 + 8 < M) {
                float* cp = C + (size_t)(row0 + 8) * ldc + gcol;
                float2 v = make_float2(acc[mi][ni][2] + b0, acc[mi][ni][3] + b1);
                if (accumulate) { float2 o = *reinterpret_cast<float2*>(cp); v.x += o.x; v.y += o.y; }
                *reinterpret_cast<float2*>(cp) = v;
            }
        }
    }
}

// ---------------- launch ----------------
extern "C" void kernel_launch(void* const* d_in, const int* in_sizes, int n_in,
                              void* d_out, int out_size) {
    const float* x   = (const float*)d_in[0];
    const float* e   = (const float*)d_in[1];
    const int*   src = (const int*)d_in[2];
    const int*   dst = (const int*)d_in[3];
    const float* Wn0 = (const float*)d_in[4];
    const float* bn0 = (const float*)d_in[5];
    const float* Wl0 = (const float*)d_in[6];
    const float* bl0 = (const float*)d_in[7];
    const float* Wn1 = (const float*)d_in[8];
    const float* bn1 = (const float*)d_in[9];
    const float* Wl1 = (const float*)d_in[10];
    const float* bl1 = (const float*)d_in[11];
    const float* Wo  = (const float*)d_in[12];
    const float* bo  = (const float*)d_in[13];
    float* out = (float*)d_out;

    float* S = nullptr;
    cudaGetSymbolAddress((void**)&S, g_scratch);
    unsigned char* BI = nullptr;
    cudaGetSymbolAddress((void**)&BI, g_bimg);

    float* Eagg = S + OFF_EAGG;
    float* P0   = S + OFF_P0;
    float* PE   = S + OFF_PE;
    float* P1   = S + OFF_P1;
    float* HCAT = S + OFF_HCAT;
    int*   I    = (int*)(S + OFF_INT);
    int* hist = I + NI_HIST;
    int* incl = I + NI_INCL;
    int* blk  = I + NI_BLK;
    int* boff = I + NI_BOFF;
    int* rp   = I + NI_RP;
    int* wp   = I + NI_WP;
    int* ps   = I + NI_PS;
    int* pe   = I + NI_PE;

    static cudaStream_t s1 = nullptr;
    static cudaEvent_t evRoot, evE, evH0, evG4a;
    if (!s1) {
        cudaStreamCreateWithFlags(&s1, cudaStreamNonBlocking);
        cudaEventCreateWithFlags(&evRoot, cudaEventDisableTiming);
        cudaEventCreateWithFlags(&evE,    cudaEventDisableTiming);
        cudaEventCreateWithFlags(&evH0,   cudaEventDisableTiming);
        cudaEventCreateWithFlags(&evG4a,  cudaEventDisableTiming);
    }

    cudaFuncSetAttribute(gemm_mma,
                         cudaFuncAttributeMaxDynamicSharedMemorySize, SM_TOTAL);

    const int MT = (NN + 127) / 128;          // 391 m-tiles
    const dim3 G4T(4, MT), G2T(2, MT);
    const int GW = (NN * 32 + 255) / 256;     // warp-per-node grids

    // fork root
    cudaEventRecord(evRoot, 0);
    cudaStreamWaitEvent(s1, evRoot, 0);

    // s1: CSR build + edge-feature gather
    zero_hist<<<(NN + 255) / 256, 256, 0, s1>>>(hist);
    hist_k<<<(NE + 255) / 256, 256, 0, s1>>>(dst, hist);
    scanA<<<49, 1024, 0, s1>>>(hist, incl, blk);
    scanB<<<1, 64, 0, s1>>>(blk, boff);
    scanC<<<49, 1024, 0, s1>>>(incl, boff, hist, rp, wp);
    permute_k<<<(NE + 255) / 256, 256, 0, s1>>>(src, dst, wp, ps, pe);
    gather_e<<<GW, 256, 0, s1>>>(e, rp, pe, Eagg);
    cudaEventRecord(evE, s1);

    // s0: weight images, G1: x @ [Wn0u | Wl0] -> P0
    prep_B<<<8, 128>>>(Wn0, Wl0, Wn1, Wl1, Wo, BI);
    gemm_mma<<<G4T, 256, SM_TOTAL>>>(x, D, BI + 0 * 65536, P0, 256, nullptr, 0, NN);

    // s0: G2: Eagg @ [Wn0e | Wn1e] -> PE   (needs Eagg)
    cudaStreamWaitEvent(0, evE, 0);
    gemm_mma<<<G4T, 256, SM_TOTAL>>>(Eagg, D, BI + 2 * 65536, PE, 256, nullptr, 0, NN);

    // s0: fused gather + epilogue, layer 0 -> HCAT cols 0-127
    gather_epi<<<GW, 256>>>(P0, P0 + 128, PE, rp, ps, bn0, bl0, HCAT);
    cudaEventRecord(evH0, 0);

    // s1: G4a: out = h1 @ Wo_top + bo  (overlaps G3)
    cudaStreamWaitEvent(s1, evH0, 0);
    gemm_mma<<<G2T, 256, SM_TOTAL, s1>>>(HCAT, 256, BI + 6 * 65536, out, 128, bo, 0, NN);
    cudaEventRecord(evG4a, s1);

    // s0: G3: h1 @ [Wn1u | Wl1] -> P1
    gemm_mma<<<G4T, 256, SM_TOTAL>>>(HCAT, 256, BI + 4 * 65536, P1, 256, nullptr, 0, NN);

    // s0: fused gather + epilogue, layer 1 -> HCAT cols 128-255
    gather_epi<<<GW, 256>>>(P1, P1 + 128, PE + 128, rp, ps, bn1, bl1, HCAT + 128);

    // s0: G4b: out += h2 @ Wo_bot   (join s1)
    cudaStreamWaitEvent(0, evG4a, 0);
    gemm_mma<<<G2T, 256, SM_TOTAL>>>(HCAT + 128, 256, BI + 7 * 65536, out, 128, nullptr, 1, NN);
}

// round 7
// speedup vs baseline: 2.1170x; 1.1782x over previous
#include <cuda_runtime.h>
#include <cuda_bf16.h>
#include <cstdint>

#define NN 50000
#define NE 800000
#define D  128

static __device__ __forceinline__ float rrelu_f(float x) {
    const float SLOPE = (1.0f/8.0f + 1.0f/3.0f) * 0.5f;
    return x >= 0.0f ? x : x * SLOPE;
}

// ---------------- scratch layout (floats) ----------------
#define ND        (NN * D)                 // 6,400,000
#define OFF_EAGG  0
#define OFF_P0    (ND)                     // 50k x 256: [T0A | T0B]
#define OFF_PE    (3 * ND)                 // 50k x 256: [EW0 | EW1]
#define OFF_P1    (5 * ND)                 // 50k x 256: [T1A | T1B]
#define OFF_HCAT  (7 * ND)                 // 50k x 256
#define OFF_INT   (9 * ND)                 // int area
#define NI_HIST 0
#define NI_INCL 50176
#define NI_BLK  100352
#define NI_BOFF 100416
#define NI_RP   100480        // 50001 entries
#define NI_WP   150912
#define NI_PS   201088        // src[perm]  (800000)
#define NI_PE   1001088       // edge id perm (800000)
#define NI_TOTAL 1801088
#define SCRATCH_N (OFF_INT + NI_TOTAL)

__device__ float g_scratch[SCRATCH_N];

// bf16 weight images: 8 chunks x 64KB. Chunk = hi[128][128] bf16 (Bt layout
// [n][k], row stride 256B) then lo[128][128]. Chunk order:
// 0:Wn0u 1:Wl0 2:Wn0e 3:Wn1e 4:Wn1u 5:Wl1 6:Wo[0:128] 7:Wo[128:256]
__device__ __align__(16) unsigned char g_bimg[8 * 65536];

// ---------------- PTX helpers ----------------
__device__ __forceinline__ uint32_t smem_u32(const void* p) {
    uint32_t a;
    asm("{ .reg .u64 t; cvta.to.shared.u64 t, %1; cvt.u32.u64 %0, t; }" : "=r"(a) : "l"(p));
    return a;
}

__device__ __forceinline__ void ldsm_x4(uint32_t addr, uint32_t* r) {
    asm volatile("ldmatrix.sync.aligned.m8n8.x4.shared.b16 {%0,%1,%2,%3}, [%4];"
                 : "=r"(r[0]), "=r"(r[1]), "=r"(r[2]), "=r"(r[3]) : "r"(addr));
}

__device__ __forceinline__ void mma_bf16(float* c, const uint32_t* a,
                                         uint32_t b0, uint32_t b1) {
    asm volatile("mma.sync.aligned.m16n8k16.row.col.f32.bf16.bf16.f32 "
                 "{%0,%1,%2,%3}, {%4,%5,%6,%7}, {%8,%9}, {%0,%1,%2,%3};"
                 : "+f"(c[0]), "+f"(c[1]), "+f"(c[2]), "+f"(c[3])
                 : "r"(a[0]), "r"(a[1]), "r"(a[2]), "r"(a[3]), "r"(b0), "r"(b1));
}

// ---------------- CSR build ----------------
__global__ void zero_hist(int* hist) {
    int i = blockIdx.x * blockDim.x + threadIdx.x;
    if (i < NN) hist[i] = 0;
}

__global__ void hist_k(const int* __restrict__ dst, int* __restrict__ hist) {
    int i = blockIdx.x * blockDim.x + threadIdx.x;
    if (i < NE) atomicAdd(hist + __ldg(dst + i), 1);
}

__global__ void scanA(const int* __restrict__ hist, int* __restrict__ incl,
                      int* __restrict__ blk) {
    __shared__ int s[1024];
    int t = threadIdx.x;
    int i = blockIdx.x * 1024 + t;
    int v = (i < NN) ? hist[i] : 0;
    s[t] = v;
    __syncthreads();
#pragma unroll
    for (int off = 1; off < 1024; off <<= 1) {
        int add = (t >= off) ? s[t - off] : 0;
        __syncthreads();
        s[t] += add;
        __syncthreads();
    }
    incl[i] = s[t];
    if (t == 1023) blk[blockIdx.x] = s[t];
}

__global__ void scanB(const int* __restrict__ blk, int* __restrict__ boff) {
    __shared__ int s[64];
    int t = threadIdx.x;
    if (t < 49) s[t] = blk[t];
    __syncthreads();
    if (t == 0) {
        int run = 0;
        for (int b = 0; b < 49; b++) { int v = s[b]; s[b] = run; run += v; }
    }
    __syncthreads();
    if (t < 49) boff[t] = s[t];
}

__global__ void scanC(const int* __restrict__ incl, const int* __restrict__ boff,
                      const int* __restrict__ hist,
                      int* __restrict__ rp, int* __restrict__ wp) {
    int t = threadIdx.x;
    int i = blockIdx.x * 1024 + t;
    if (i < NN) {
        int inc = incl[i] + boff[blockIdx.x];
        rp[i + 1] = inc;
        wp[i] = inc - hist[i];
    }
    if (i == 0) rp[0] = 0;
}

__global__ void permute_k(const int* __restrict__ src, const int* __restrict__ dst,
                          int* __restrict__ wp,
                          int* __restrict__ ps, int* __restrict__ pe) {
    int i = blockIdx.x * blockDim.x + threadIdx.x;
    if (i >= NE) return;
    int d = __ldg(dst + i);
    int pos = atomicAdd(wp + d, 1);
    ps[pos] = __ldg(src + i);
    pe[pos] = i;
}

// ---------------- CSR gathers ----------------
__global__ void gather_e(const float* __restrict__ e,
                         const int* __restrict__ rp,
                         const int* __restrict__ pe,
                         float* __restrict__ Eagg) {
    int w    = (blockIdx.x * blockDim.x + threadIdx.x) >> 5;
    int lane = threadIdx.x & 31;
    if (w >= NN) return;
    int beg = __ldg(rp + w), end = __ldg(rp + w + 1);
    float4 acc = make_float4(0.f, 0.f, 0.f, 0.f);
    for (int j = beg; j < end; j += 32) {
        int m = min(32, end - j);
        int eid = (lane < m) ? __ldg(pe + j + lane) : 0;
        for (int t = 0; t < m; t++) {
            int et = __shfl_sync(0xffffffffu, eid, t);
            float4 v = *reinterpret_cast<const float4*>(e + (size_t)et * D + lane * 4);
            acc.x += v.x; acc.y += v.y; acc.z += v.z; acc.w += v.w;
        }
    }
    *reinterpret_cast<float4*>(Eagg + (size_t)w * D + lane * 4) = acc;
}

__global__ void gather_epi(const float* __restrict__ T,    // ld 256, cols 0-127
                           const float* __restrict__ Tb,   // ld 256 (self-loop proj)
                           const float* __restrict__ EW,   // ld 256
                           const int* __restrict__ rp,
                           const int* __restrict__ ps,
                           const float* __restrict__ bn,
                           const float* __restrict__ bl,
                           float* __restrict__ hc) {       // ld 256
    int w    = (blockIdx.x * blockDim.x + threadIdx.x) >> 5;
    int lane = threadIdx.x & 31;
    if (w >= NN) return;
    int beg = __ldg(rp + w), end = __ldg(rp + w + 1);
    float4 acc = make_float4(0.f, 0.f, 0.f, 0.f);
    for (int j = beg; j < end; j += 32) {
        int m = min(32, end - j);
        int sidx = (lane < m) ? __ldg(ps + j + lane) : 0;
        for (int t = 0; t < m; t++) {
            int s = __shfl_sync(0xffffffffu, sidx, t);
            float4 v = *reinterpret_cast<const float4*>(T + (size_t)s * 256 + lane * 4);
            acc.x += v.x; acc.y += v.y; acc.z += v.z; acc.w += v.w;
        }
    }
    int cn = end - beg;
    float inv = 1.0f / fmaxf((float)cn, 1.0f);
    float g = (cn > 0) ? 1.0f : 0.0f;
    float4 ew = *reinterpret_cast<const float4*>(EW + (size_t)w * 256 + lane * 4);
    float4 tb = *reinterpret_cast<const float4*>(Tb + (size_t)w * 256 + lane * 4);
    float4 b4 = *reinterpret_cast<const float4*>(bn + lane * 4);
    float4 l4 = *reinterpret_cast<const float4*>(bl + lane * 4);
    float4 o;
    o.x = rrelu_f((acc.x + ew.x) * inv + g * b4.x + tb.x + l4.x);
    o.y = rrelu_f((acc.y + ew.y) * inv + g * b4.y + tb.y + l4.y);
    o.z = rrelu_f((acc.z + ew.z) * inv + g * b4.z + tb.z + l4.z);
    o.w = rrelu_f((acc.w + ew.w) * inv + g * b4.w + tb.w + l4.w);
    *reinterpret_cast<float4*>(hc + (size_t)w * 256 + lane * 4) = o;
}

// ---------------- weight image prep ----------------
__global__ void prep_B(const float* __restrict__ Wn0, const float* __restrict__ Wl0,
                       const float* __restrict__ Wn1, const float* __restrict__ Wl1,
                       const float* __restrict__ Wo, unsigned char* __restrict__ img) {
    int ci = blockIdx.x;
    const float* W;
    switch (ci) {
        case 0: W = Wn0; break;
        case 1: W = Wl0; break;
        case 2: W = Wn0 + 128 * 128; break;
        case 3: W = Wn1 + 128 * 128; break;
        case 4: W = Wn1; break;
        case 5: W = Wl1; break;
        case 6: W = Wo; break;
        default: W = Wo + 128 * 128; break;
    }
    unsigned char* hi_img = img + ci * 65536;
    unsigned char* lo_img = hi_img + 32768;

    __shared__ float sw[64][129];
    int t = threadIdx.x;  // 128
    for (int kt = 0; kt < 2; kt++) {
        for (int i = t; i < 64 * 128; i += 128)
            sw[i >> 7][i & 127] = W[kt * 64 * 128 + i];
        __syncthreads();
        int n = t;
#pragma unroll
        for (int u = 0; u < 8; u++) {
            union { __nv_bfloat16 h[8]; uint4 v; } hi;
            union { __nv_bfloat16 h[8]; uint4 v; } lo;
#pragma unroll
            for (int j = 0; j < 8; j++) {
                float f = sw[u * 8 + j][n];
                __nv_bfloat16 hb = __float2bfloat16(f);
                hi.h[j] = hb;
                lo.h[j] = __float2bfloat16(f - __bfloat162float(hb));
            }
            uint32_t off = (uint32_t)(n * 256 + kt * 128 + u * 16);
            *reinterpret_cast<uint4*>(hi_img + off) = hi.v;
            *reinterpret_cast<uint4*>(lo_img + off) = lo.v;
        }
        __syncthreads();
    }
}

// ---------------- HMMA bf16x3 GEMM: 128 x (128*NCH) tile, K=128, 512 thr ----
// smem: A hi/lo [128][136]bf16 (34816 B each), then NCH chunk images hi/lo.
#define SA_HI 0
#define SA_LO 34816
#define SB_BASE 69632
#define CHUNK_SM 69632                       // hi+lo per chunk in smem
#define SM_SZ(NCH) (SB_BASE + (NCH) * CHUNK_SM)

template<int NCH>
__global__ __launch_bounds__(512, 1)
void gemm_mma(const float* __restrict__ A, int lda,
              const unsigned char* __restrict__ Bimg,
              float* __restrict__ C, int ldc,
              const float* __restrict__ bias, int accumulate, int M) {
    constexpr int MI = 2 * NCH;              // 16-row m-tiles per warp
    constexpr int NW = 4 * NCH;              // warps across N
    extern __shared__ unsigned char smem[];
    uint32_t sb = smem_u32(smem);
    int tid  = threadIdx.x;
    int lane = tid & 31;
    int wid  = tid >> 5;
    int wn   = wid % NW;                     // 32-col slice
    int wm   = wid / NW;                     // (16/NW) m-slices of 32*NCH rows
    int bm   = blockIdx.y * 128;

    float acc[MI][4][4];
#pragma unroll
    for (int mi = 0; mi < MI; mi++)
#pragma unroll
        for (int ni = 0; ni < 4; ni++)
#pragma unroll
            for (int q = 0; q < 4; q++) acc[mi][ni][q] = 0.f;

    // ---- A: global f32 -> smem bf16 hi/lo (each thread: 1/4 row) ----
    {
        int r = tid >> 2;            // 0..127
        int q = tid & 3;             // 32-col quarter
        bool valid = (bm + r) < M;
        const float4* ap = reinterpret_cast<const float4*>(
            A + (size_t)(bm + r) * lda + q * 32);
        float4 z4 = make_float4(0.f, 0.f, 0.f, 0.f);
#pragma unroll
        for (int u = 0; u < 4; u++) {
            float4 f0 = valid ? ap[u * 2]     : z4;
            float4 f1 = valid ? ap[u * 2 + 1] : z4;
            float fs[8] = {f0.x, f0.y, f0.z, f0.w, f1.x, f1.y, f1.z, f1.w};
            union { __nv_bfloat16 b[8]; uint4 v; } hi;
            union { __nv_bfloat16 b[8]; uint4 v; } lo;
#pragma unroll
            for (int j = 0; j < 8; j++) {
                __nv_bfloat16 hb = __float2bfloat16(fs[j]);
                hi.b[j] = hb;
                lo.b[j] = __float2bfloat16(fs[j] - __bfloat162float(hb));
            }
            uint32_t off = (uint32_t)(r * 272 + q * 64 + u * 16);
            *reinterpret_cast<uint4*>(smem + SA_HI + off) = hi.v;
            *reinterpret_cast<uint4*>(smem + SA_LO + off) = lo.v;
        }
    }
    // ---- B: NCH chunk images -> smem (re-strided 256 -> 272) ----
#pragma unroll
    for (int c = 0; c < NCH; c++) {
        const unsigned char* ch = Bimg + (size_t)(blockIdx.x * NCH + c) * 65536;
        unsigned char* db = smem + SB_BASE + c * CHUNK_SM;
#pragma unroll
        for (int i = 0; i < 4; i++) {
            int linear = tid + i * 512;       // 0..2047
            int row = linear >> 4;            // 0..127
            int c16 = linear & 15;
            uint32_t soff = (uint32_t)(row * 256 + c16 * 16);
            uint32_t doff = (uint32_t)(row * 272 + c16 * 16);
            *reinterpret_cast<uint4*>(db + doff) =
                *reinterpret_cast<const uint4*>(ch + soff);
            *reinterpret_cast<uint4*>(db + 34816 + doff) =
                *reinterpret_cast<const uint4*>(ch + 32768 + soff);
        }
    }
    __syncthreads();

    // ---- MMA over 8 k16 steps ----
    uint32_t a_row = (uint32_t)(wm * (32 * NCH) + (lane & 15));
    uint32_t a_cb  = (uint32_t)((lane >> 4) * 16);
    uint32_t sbB   = sb + SB_BASE + (wn >> 2) * CHUNK_SM;
    uint32_t b_n   = (uint32_t)((wn & 3) * 32 + ((lane >> 4) << 3) + (lane & 7));
    uint32_t b_cb  = (uint32_t)(((lane >> 3) & 1) * 16);
#pragma unroll
    for (int ks = 0; ks < 8; ks++) {
        uint32_t kb = (uint32_t)(ks * 32);
        uint32_t Ahi[MI][4], Alo[MI][4];
#pragma unroll
        for (int mi = 0; mi < MI; mi++) {
            ldsm_x4(sb + SA_HI + (a_row + mi * 16) * 272 + kb + a_cb, Ahi[mi]);
            ldsm_x4(sb + SA_LO + (a_row + mi * 16) * 272 + kb + a_cb, Alo[mi]);
        }
#pragma unroll
        for (int nj = 0; nj < 2; nj++) {
            uint32_t bh[4], bl[4];
            uint32_t baddr = (b_n + nj * 16) * 272 + kb + b_cb;
            ldsm_x4(sbB + baddr, bh);
            ldsm_x4(sbB + 34816 + baddr, bl);
#pragma unroll
            for (int mi = 0; mi < MI; mi++) {
                mma_bf16(acc[mi][2 * nj],     Ahi[mi], bh[0], bh[1]);
                mma_bf16(acc[mi][2 * nj],     Ahi[mi], bl[0], bl[1]);
                mma_bf16(acc[mi][2 * nj],     Alo[mi], bh[0], bh[1]);
                mma_bf16(acc[mi][2 * nj + 1], Ahi[mi], bh[2], bh[3]);
                mma_bf16(acc[mi][2 * nj + 1], Ahi[mi], bl[2], bl[3]);
                mma_bf16(acc[mi][2 * nj + 1], Alo[mi], bh[2], bh[3]);
            }
        }
    }

    // ---- epilogue ----
    int lrow = lane >> 2;
    int lcol = (lane & 3) * 2;
#pragma unroll
    for (int mi = 0; mi < MI; mi++) {
        int row0 = bm + wm * (32 * NCH) + mi * 16 + lrow;
#pragma unroll
        for (int ni = 0; ni < 4; ni++) {
            int gcol = blockIdx.x * (128 * NCH) + wn * 32 + ni * 8 + lcol;
            float b0 = 0.f, b1 = 0.f;
            if (bias) {
                b0 = __ldg(bias + gcol);
                b1 = __ldg(bias + gcol + 1);
            }
            if (row0 < M) {
                float* cp = C + (size_t)row0 * ldc + gcol;
                float2 v = make_float2(acc[mi][ni][0] + b0, acc[mi][ni][1] + b1);
                if (accumulate) { float2 o = *reinterpret_cast<float2*>(cp); v.x += o.x; v.y += o.y; }
                *reinterpret_cast<float2*>(cp) = v;
            }
            if (row0 + 8 < M) {
                float* cp = C + (size_t)(row0 + 8) * ldc + gcol;
                float2 v = make_float2(acc[mi][ni][2] + b0, acc[mi][ni][3] + b1);
                if (accumulate) { float2 o = *reinterpret_cast<float2*>(cp); v.x += o.x; v.y += o.y; }
                *reinterpret_cast<float2*>(cp) = v;
            }
        }
    }
}

// ---------------- launch ----------------
extern "C" void kernel_launch(void* const* d_in, const int* in_sizes, int n_in,
                              void* d_out, int out_size) {
    const float* x   = (const float*)d_in[0];
    const float* e   = (const float*)d_in[1];
    const int*   src = (const int*)d_in[2];
    const int*   dst = (const int*)d_in[3];
    const float* Wn0 = (const float*)d_in[4];
    const float* bn0 = (const float*)d_in[5];
    const float* Wl0 = (const float*)d_in[6];
    const float* bl0 = (const float*)d_in[7];
    const float* Wn1 = (const float*)d_in[8];
    const float* bn1 = (const float*)d_in[9];
    const float* Wl1 = (const float*)d_in[10];
    const float* bl1 = (const float*)d_in[11];
    const float* Wo  = (const float*)d_in[12];
    const float* bo  = (const float*)d_in[13];
    float* out = (float*)d_out;

    float* S = nullptr;
    cudaGetSymbolAddress((void**)&S, g_scratch);
    unsigned char* BI = nullptr;
    cudaGetSymbolAddress((void**)&BI, g_bimg);

    float* Eagg = S + OFF_EAGG;
    float* P0   = S + OFF_P0;
    float* PE   = S + OFF_PE;
    float* P1   = S + OFF_P1;
    float* HCAT = S + OFF_HCAT;
    int*   I    = (int*)(S + OFF_INT);
    int* hist = I + NI_HIST;
    int* incl = I + NI_INCL;
    int* blk  = I + NI_BLK;
    int* boff = I + NI_BOFF;
    int* rp   = I + NI_RP;
    int* wp   = I + NI_WP;
    int* ps   = I + NI_PS;
    int* pe   = I + NI_PE;

    static cudaStream_t s1 = nullptr;
    static cudaEvent_t evRoot, evE, evH0, evG4a;
    if (!s1) {
        cudaStreamCreateWithFlags(&s1, cudaStreamNonBlocking);
        cudaEventCreateWithFlags(&evRoot, cudaEventDisableTiming);
        cudaEventCreateWithFlags(&evE,    cudaEventDisableTiming);
        cudaEventCreateWithFlags(&evH0,   cudaEventDisableTiming);
        cudaEventCreateWithFlags(&evG4a,  cudaEventDisableTiming);
    }

    cudaFuncSetAttribute(gemm_mma<2>,
                         cudaFuncAttributeMaxDynamicSharedMemorySize, SM_SZ(2));
    cudaFuncSetAttribute(gemm_mma<1>,
                         cudaFuncAttributeMaxDynamicSharedMemorySize, SM_SZ(1));

    const int MT = (NN + 127) / 128;          // 391 m-tiles
    const dim3 GT(1, MT);
    const int GW = (NN * 32 + 255) / 256;     // warp-per-node grids

    // fork root
    cudaEventRecord(evRoot, 0);
    cudaStreamWaitEvent(s1, evRoot, 0);

    // s1: CSR build + edge-feature gather
    zero_hist<<<(NN + 255) / 256, 256, 0, s1>>>(hist);
    hist_k<<<(NE + 255) / 256, 256, 0, s1>>>(dst, hist);
    scanA<<<49, 1024, 0, s1>>>(hist, incl, blk);
    scanB<<<1, 64, 0, s1>>>(blk, boff);
    scanC<<<49, 1024, 0, s1>>>(incl, boff, hist, rp, wp);
    permute_k<<<(NE + 255) / 256, 256, 0, s1>>>(src, dst, wp, ps, pe);
    gather_e<<<GW, 256, 0, s1>>>(e, rp, pe, Eagg);
    cudaEventRecord(evE, s1);

    // s0: weight images, G1: x @ [Wn0u | Wl0] -> P0
    prep_B<<<8, 128>>>(Wn0, Wl0, Wn1, Wl1, Wo, BI);
    gemm_mma<2><<<GT, 512, SM_SZ(2)>>>(x, D, BI + 0 * 65536, P0, 256, nullptr, 0, NN);

    // s0: G2: Eagg @ [Wn0e | Wn1e] -> PE   (needs Eagg)
    cudaStreamWaitEvent(0, evE, 0);
    gemm_mma<2><<<GT, 512, SM_SZ(2)>>>(Eagg, D, BI + 2 * 65536, PE, 256, nullptr, 0, NN);

    // s0: fused gather + epilogue, layer 0 -> HCAT cols 0-127
    gather_epi<<<GW, 256>>>(P0, P0 + 128, PE, rp, ps, bn0, bl0, HCAT);
    cudaEventRecord(evH0, 0);

    // s1: G4a: out = h1 @ Wo_top + bo  (overlaps G3)
    cudaStreamWaitEvent(s1, evH0, 0);
    gemm_mma<1><<<GT, 512, SM_SZ(1), s1>>>(HCAT, 256, BI + 6 * 65536, out, 128, bo, 0, NN);
    cudaEventRecord(evG4a, s1);

    // s0: G3: h1 @ [Wn1u | Wl1] -> P1
    gemm_mma<2><<<GT, 512, SM_SZ(2)>>>(HCAT, 256, BI + 4 * 65536, P1, 256, nullptr, 0, NN);

    // s0: fused gather + epilogue, layer 1 -> HCAT cols 128-255
    gather_epi<<<GW, 256>>>(P1, P1 + 128, PE + 128, rp, ps, bn1, bl1, HCAT + 128);

    // s0: G4b: out += h2 @ Wo_bot   (join s1)
    cudaStreamWaitEvent(0, evG4a, 0);
    gemm_mma<1><<<GT, 512, SM_SZ(1)>>>(HCAT + 128, 256, BI + 7 * 65536, out, 128, nullptr, 1, NN);
}